// round 7
// baseline (speedup 1.0000x reference)
#include <cuda_runtime.h>
#include <cstdint>
#include <math.h>

// ---------------------------------------------------------------- dims
#define B_DIM 8192
#define H_DIM 2048
constexpr int KTOT = 4096;            // folded K: 2048 (x_t) + 2048 (state)

// GEMM tiling
constexpr int BM = 128;               // batch rows per CTA
constexpr int BN = 128;               // H cols per CTA (cand & gate both)
constexpr int BK = 16;
constexpr int STAGES = 4;
constexpr int NTHREADS = 512;         // 16 warps: 4 along M x 4 along N; warp tile 32x32
constexpr int NITER = KTOT / BK;      // 256
constexpr int T_LD = 24;              // floats per smem tile row (16 data + 8 pad) -> conflict-free LDS.64

struct SmemStage {
    float A [BM * T_LD];              // [m][k]  3072 floats
    float Bc[BN * T_LD];              // [n][k]  3072
    float Bg[BN * T_LD];              // [n][k]  3072
};
constexpr int SMEM_TOTAL = (int)(sizeof(SmemStage) * STAGES);   // 147456 B

// ---------------------------------------------------------------- scratch (device globals)
// Weights: n-major [j][k], folded (W + U on k>=2048), rna-tf32, k-permuted within 8-blocks.
__device__ float g_WcT[(size_t)H_DIM * KTOT];
__device__ float g_WgT[(size_t)H_DIM * KTOT];
// Activations: [r][k], rna-tf32, k-permuted within 8-blocks.
__device__ float g_xr [(size_t)B_DIM * H_DIM];
__device__ float g_sr [(size_t)B_DIM * H_DIM];
__device__ float g_h  [(size_t)B_DIM * H_DIM];  // h_new before layernorm

// ---------------------------------------------------------------- helpers
__device__ __forceinline__ void cp_async16(void* dst, const void* src) {
    uint32_t s = (uint32_t)__cvta_generic_to_shared(dst);
    asm volatile("cp.async.cg.shared.global [%0], [%1], 16;" :: "r"(s), "l"(src));
}
__device__ __forceinline__ void cp_commit() { asm volatile("cp.async.commit_group;"); }
template<int N> __device__ __forceinline__ void cp_wait() {
    asm volatile("cp.async.wait_group %0;" :: "n"(N));
}
__device__ __forceinline__ uint32_t f2tf32(float f) {
    uint32_t r; asm("cvt.rna.tf32.f32 %0, %1;" : "=r"(r) : "f"(f)); return r;
}
__device__ __forceinline__ void mma8(float* c, uint32_t a0, uint32_t a1, uint32_t a2, uint32_t a3,
                                     uint32_t b0, uint32_t b1) {
    asm volatile(
        "mma.sync.aligned.m16n8k8.row.col.f32.tf32.tf32.f32 "
        "{%0,%1,%2,%3}, {%4,%5,%6,%7}, {%8,%9}, {%0,%1,%2,%3};"
        : "+f"(c[0]), "+f"(c[1]), "+f"(c[2]), "+f"(c[3])
        : "r"(a0), "r"(a1), "r"(a2), "r"(a3), "r"(b0), "r"(b1));
}

// ---------------------------------------------------------------- prep: weights
// g_WT[j][kp] = rna( W[k][j] + (k>=2048 ? U[k-2048][j] : 0) ), kp = in-8-block frag permutation
__global__ void prep_weights_t(const float* __restrict__ Wc, const float* __restrict__ Uc,
                               const float* __restrict__ Wg, const float* __restrict__ Ug) {
    __shared__ float tc[32][33];
    __shared__ float tg[32][33];
    int tx = threadIdx.x, ty = threadIdx.y;        // 32 x 8
    int k0 = blockIdx.x * 32, j0 = blockIdx.y * 32;
    #pragma unroll
    for (int r = 0; r < 4; r++) {
        int kr = k0 + ty + r * 8;
        size_t idx = (size_t)kr * H_DIM + j0 + tx;
        float vc = Wc[idx], vg = Wg[idx];
        if (kr >= H_DIM) {
            size_t iu = (size_t)(kr - H_DIM) * H_DIM + j0 + tx;
            vc += Uc[iu]; vg += Ug[iu];
        }
        tc[ty + r * 8][tx] = __uint_as_float(f2tf32(vc));
        tg[ty + r * 8][tx] = __uint_as_float(f2tf32(vg));
    }
    __syncthreads();
    // permuted k within each 8-block: p -> (p%4)*2 + p/4
    int kp = (tx & ~7) | (((tx & 3) << 1) | ((tx >> 2) & 1));
    #pragma unroll
    for (int r = 0; r < 4; r++) {
        int jr = j0 + ty + r * 8;
        g_WcT[(size_t)jr * KTOT + k0 + kp] = tc[tx][ty + r * 8];
        g_WgT[(size_t)jr * KTOT + k0 + kp] = tg[tx][ty + r * 8];
    }
}

// ---------------------------------------------------------------- prep: activations
// interleave pairs: out[2i]=rna(in[i]), out[2i+1]=rna(in[i+4]) within each 8-block
__global__ void prep_act(const float4* __restrict__ x_t, const float4* __restrict__ state) {
    size_t i = (size_t)blockIdx.x * blockDim.x + threadIdx.x;   // over B*H/8 (8 floats per thread)
    size_t base = i * 2;                                        // float4 index of first half
    float4 a0 = x_t[base],   a1 = x_t[base + 1];
    float4 s0 = state[base], s1 = state[base + 1];
    float4 oa0, oa1, os0, os1;
    oa0.x = __uint_as_float(f2tf32(a0.x)); oa0.y = __uint_as_float(f2tf32(a1.x));
    oa0.z = __uint_as_float(f2tf32(a0.y)); oa0.w = __uint_as_float(f2tf32(a1.y));
    oa1.x = __uint_as_float(f2tf32(a0.z)); oa1.y = __uint_as_float(f2tf32(a1.z));
    oa1.z = __uint_as_float(f2tf32(a0.w)); oa1.w = __uint_as_float(f2tf32(a1.w));
    os0.x = __uint_as_float(f2tf32(s0.x)); os0.y = __uint_as_float(f2tf32(s1.x));
    os0.z = __uint_as_float(f2tf32(s0.y)); os0.w = __uint_as_float(f2tf32(s1.y));
    os1.x = __uint_as_float(f2tf32(s0.z)); os1.y = __uint_as_float(f2tf32(s1.z));
    os1.z = __uint_as_float(f2tf32(s0.w)); os1.w = __uint_as_float(f2tf32(s1.w));
    ((float4*)g_xr)[base]     = oa0;
    ((float4*)g_xr)[base + 1] = oa1;
    ((float4*)g_sr)[base]     = os0;
    ((float4*)g_sr)[base + 1] = os1;
}

// ---------------------------------------------------------------- stage loader (512 threads)
__device__ __forceinline__ void load_stage(
    SmemStage& st, int ks, int tid, int rowBase, int colBase)
{
    const int k0 = ks * BK;
    const float* Asrc; int ka;
    if (k0 < H_DIM) { Asrc = g_xr; ka = k0; }
    else            { Asrc = g_sr; ka = k0 - H_DIM; }
    // A: 128 rows x 16 floats = 512 x 16B chunks (1 per thread)
    {
        int row = tid >> 2, ch = (tid & 3) * 4;
        cp_async16(&st.A[row * T_LD + ch],
                   Asrc + (size_t)(rowBase + row) * H_DIM + ka + ch);
    }
    // Bc/Bg: 128 n-rows x 16 floats each (1 chunk of each per thread)
    {
        int n = tid >> 2, ch = (tid & 3) * 4;
        size_t off = (size_t)(colBase + n) * KTOT + k0 + ch;
        cp_async16(&st.Bc[n * T_LD + ch], g_WcT + off);
        cp_async16(&st.Bg[n * T_LD + ch], g_WgT + off);
    }
    cp_commit();
}

// ---------------------------------------------------------------- fused dual-GEMM + gate epilogue
__global__ void __launch_bounds__(NTHREADS, 1)
gemm_kernel(const float* __restrict__ state,
            const float* __restrict__ bc,  const float* __restrict__ bg,
            const float* __restrict__ log_step)
{
    extern __shared__ char smem_raw[];
    SmemStage* smem = (SmemStage*)smem_raw;

    const int rowBase = blockIdx.y * BM;
    const int colBase = blockIdx.x * BN;
    const int tid  = threadIdx.x;
    const int wid  = tid >> 5, lane = tid & 31;
    const int wm   = wid & 3,  wn   = wid >> 2;      // 4 warps along M, 4 along N
    const int g    = lane >> 2, t4  = lane & 3;

    float accC[2][4][4];     // [mt][nt][frag]
    float accG[2][4][4];
    #pragma unroll
    for (int a = 0; a < 2; a++)
        #pragma unroll
        for (int b = 0; b < 4; b++)
            #pragma unroll
            for (int c = 0; c < 4; c++) { accC[a][b][c] = 0.f; accG[a][b][c] = 0.f; }

    for (int s = 0; s < STAGES - 1; s++)
        load_stage(smem[s], s, tid, rowBase, colBase);

    for (int kt = 0; kt < NITER; kt++) {
        cp_wait<STAGES - 2>();
        __syncthreads();

        int nxt = kt + STAGES - 1;
        if (nxt < NITER)
            load_stage(smem[nxt % STAGES], nxt, tid, rowBase, colBase);
        else
            cp_commit();                         // keep group-count invariant

        SmemStage& st = smem[kt % STAGES];
        #pragma unroll
        for (int kk = 0; kk < 2; kk++) {
            const int kb = kk * 8 + t4 * 2;      // frag pair offset (k-permuted layout)
            // A frags: (a0,a2) then (a1,a3) via LDS.64
            float2 aLo[2], aHi[2];
            #pragma unroll
            for (int mt = 0; mt < 2; mt++) {
                int r = wm * 32 + mt * 16 + g;
                aLo[mt] = *(const float2*)&st.A[r * T_LD + kb];
                aHi[mt] = *(const float2*)&st.A[(r + 8) * T_LD + kb];
            }
            // B frags: (b0,b1) via LDS.64
            float2 fc[4], fg[4];
            #pragma unroll
            for (int nt = 0; nt < 4; nt++) {
                int n = wn * 32 + nt * 8 + g;
                fc[nt] = *(const float2*)&st.Bc[n * T_LD + kb];
                fg[nt] = *(const float2*)&st.Bg[n * T_LD + kb];
            }
            #pragma unroll
            for (int nt = 0; nt < 4; nt++) {
                uint32_t bc0 = __float_as_uint(fc[nt].x), bc1 = __float_as_uint(fc[nt].y);
                uint32_t bg0 = __float_as_uint(fg[nt].x), bg1 = __float_as_uint(fg[nt].y);
                #pragma unroll
                for (int mt = 0; mt < 2; mt++) {
                    uint32_t a0 = __float_as_uint(aLo[mt].x), a2 = __float_as_uint(aLo[mt].y);
                    uint32_t a1 = __float_as_uint(aHi[mt].x), a3 = __float_as_uint(aHi[mt].y);
                    mma8(accC[mt][nt], a0, a1, a2, a3, bc0, bc1);
                    mma8(accG[mt][nt], a0, a1, a2, a3, bg0, bg1);
                }
            }
        }
    }

    // Epilogue: h = alpha*state + (1-alpha)*sigmoid(zg)*tanh(zc)
    #pragma unroll
    for (int nt = 0; nt < 4; nt++) {
        int j0 = colBase + wn * 32 + nt * 8 + 2 * t4;
        float bc0 = bc[j0],  bc1 = bc[j0 + 1];
        float bg0 = bg[j0],  bg1 = bg[j0 + 1];
        float al0 = expf(-expf(-log_step[j0]));      // alpha = exp(-1/exp(log_step))
        float al1 = expf(-expf(-log_step[j0 + 1]));
        #pragma unroll
        for (int mt = 0; mt < 2; mt++) {
            int r0 = rowBase + wm * 32 + mt * 16 + g;
            #pragma unroll
            for (int half = 0; half < 2; half++) {
                int r = r0 + half * 8;
                float zc0 = accC[mt][nt][half * 2]     + bc0;
                float zc1 = accC[mt][nt][half * 2 + 1] + bc1;
                float zg0 = accG[mt][nt][half * 2]     + bg0;
                float zg1 = accG[mt][nt][half * 2 + 1] + bg1;
                float s0 = state[(size_t)r * H_DIM + j0];
                float s1 = state[(size_t)r * H_DIM + j0 + 1];
                float cand0 = tanhf(zc0), cand1 = tanhf(zc1);
                float gate0 = 1.f / (1.f + expf(-zg0));
                float gate1 = 1.f / (1.f + expf(-zg1));
                float h0 = al0 * s0 + (1.f - al0) * gate0 * cand0;
                float h1 = al1 * s1 + (1.f - al1) * gate1 * cand1;
                *(float2*)&g_h[(size_t)r * H_DIM + j0] = make_float2(h0, h1);
            }
        }
    }
}

// ---------------------------------------------------------------- layernorm over H=2048
__device__ __forceinline__ float warp_sum(float v) {
    #pragma unroll
    for (int o = 16; o; o >>= 1) v += __shfl_xor_sync(0xffffffffu, v, o);
    return v;
}

__global__ void ln_kernel(const float* __restrict__ gamma, const float* __restrict__ beta,
                          float* __restrict__ out)
{
    int row = blockIdx.x;
    const float4* h = (const float4*)(g_h + (size_t)row * H_DIM);
    float4*       o = (float4*)(out + (size_t)row * H_DIM);
    const float4* gm = (const float4*)gamma;
    const float4* bt = (const float4*)beta;

    int tid = threadIdx.x;
    float4 v0 = h[tid], v1 = h[tid + 256];

    float s  = v0.x + v0.y + v0.z + v0.w + v1.x + v1.y + v1.z + v1.w;
    float sq = v0.x*v0.x + v0.y*v0.y + v0.z*v0.z + v0.w*v0.w
             + v1.x*v1.x + v1.y*v1.y + v1.z*v1.z + v1.w*v1.w;

    s  = warp_sum(s);
    sq = warp_sum(sq);
    __shared__ float sh[16];
    int wid = tid >> 5, lane = tid & 31;
    if (lane == 0) { sh[wid] = s; sh[8 + wid] = sq; }
    __syncthreads();
    float tot = 0.f, totq = 0.f;
    #pragma unroll
    for (int i = 0; i < 8; i++) { tot += sh[i]; totq += sh[8 + i]; }

    float mu  = tot * (1.f / H_DIM);
    float var = totq * (1.f / H_DIM) - mu * mu;
    float inv = rsqrtf(var + 1e-5f);

    float4 g0 = gm[tid], g1 = gm[tid + 256];
    float4 b0 = bt[tid], b1 = bt[tid + 256];
    float4 o0, o1;
    o0.x = (v0.x - mu) * inv * g0.x + b0.x;
    o0.y = (v0.y - mu) * inv * g0.y + b0.y;
    o0.z = (v0.z - mu) * inv * g0.z + b0.z;
    o0.w = (v0.w - mu) * inv * g0.w + b0.w;
    o1.x = (v1.x - mu) * inv * g1.x + b1.x;
    o1.y = (v1.y - mu) * inv * g1.y + b1.y;
    o1.z = (v1.z - mu) * inv * g1.z + b1.z;
    o1.w = (v1.w - mu) * inv * g1.w + b1.w;
    o[tid] = o0;
    o[tid + 256] = o1;
}

// ---------------------------------------------------------------- launch
extern "C" void kernel_launch(void* const* d_in, const int* in_sizes, int n_in,
                              void* d_out, int out_size) {
    const float* x_t      = (const float*)d_in[0];
    const float* state    = (const float*)d_in[1];
    const float* Wc       = (const float*)d_in[2];
    const float* Uc       = (const float*)d_in[3];
    const float* bc       = (const float*)d_in[4];
    const float* Wg       = (const float*)d_in[5];
    const float* Ug       = (const float*)d_in[6];
    const float* bg       = (const float*)d_in[7];
    const float* log_step = (const float*)d_in[8];
    const float* gamma    = (const float*)d_in[9];
    const float* beta     = (const float*)d_in[10];
    float* out = (float*)d_out;

    cudaFuncSetAttribute(gemm_kernel, cudaFuncAttributeMaxDynamicSharedMemorySize, SMEM_TOTAL);

    dim3 pgrid(KTOT / 32, H_DIM / 32);     // (128, 64)
    prep_weights_t<<<pgrid, dim3(32, 8)>>>(Wc, Uc, Wg, Ug);
    prep_act<<<(int)(((size_t)B_DIM * H_DIM / 8) / 256), 256>>>(
        (const float4*)x_t, (const float4*)state);

    dim3 grid(H_DIM / BN, B_DIM / BM);     // (16, 64) = 1024 CTAs
    gemm_kernel<<<grid, NTHREADS, SMEM_TOTAL>>>(state, bc, bg, log_step);

    ln_kernel<<<B_DIM, 256>>>(gamma, beta, out);
}

// round 8
// speedup vs baseline: 1.9938x; 1.9938x over previous
#include <cuda_runtime.h>
#include <cuda_fp16.h>
#include <cstdint>
#include <math.h>

// ---------------------------------------------------------------- dims
#define B_DIM 8192
#define H_DIM 2048
constexpr int KTOT = 4096;            // folded K: 2048 (x_t) + 2048 (state)

// GEMM tiling (fp16 operands, fp32 accumulate)
constexpr int BM = 128;               // batch rows per CTA
constexpr int BN = 128;               // H cols per CTA (cand & gate both)
constexpr int BK = 32;                // k-halves per stage (64B rows)
constexpr int STAGES = 5;
constexpr int NTHREADS = 256;         // 8 warps: 2 along M x 4 along N; warp tile 64x32
constexpr int NITER = KTOT / BK;      // 128
constexpr int T_LD = 48;              // halves per smem row (32 data + 16 pad = 96B) -> LDS.64 conflict-free

struct SmemStage {
    __half A [BM * T_LD];             // [m][k]
    __half Bc[BN * T_LD];             // [n][k]
    __half Bg[BN * T_LD];             // [n][k]
};
constexpr int SMEM_TOTAL = (int)(sizeof(SmemStage) * STAGES);   // 184320 B

// ---------------------------------------------------------------- scratch (device globals)
// Weights: n-major [j][k], folded (W+U on k>=2048), fp16-rn, k-pair-permuted per 16-block.
__device__ __half g_WcT[(size_t)H_DIM * KTOT];
__device__ __half g_WgT[(size_t)H_DIM * KTOT];
// Activations: [r][k], fp16-rn, same k-pair permutation.
__device__ __half g_xr [(size_t)B_DIM * H_DIM];
__device__ __half g_sr [(size_t)B_DIM * H_DIM];
__device__ float  g_h  [(size_t)B_DIM * H_DIM];  // h_new before layernorm

// ---------------------------------------------------------------- helpers
__device__ __forceinline__ void cp_async16(void* dst, const void* src) {
    uint32_t s = (uint32_t)__cvta_generic_to_shared(dst);
    asm volatile("cp.async.cg.shared.global [%0], [%1], 16;" :: "r"(s), "l"(src));
}
__device__ __forceinline__ void cp_commit() { asm volatile("cp.async.commit_group;"); }
template<int N> __device__ __forceinline__ void cp_wait() {
    asm volatile("cp.async.wait_group %0;" :: "n"(N));
}
__device__ __forceinline__ void mma16(float* c, uint32_t a0, uint32_t a1, uint32_t a2, uint32_t a3,
                                      uint32_t b0, uint32_t b1) {
    asm volatile(
        "mma.sync.aligned.m16n8k16.row.col.f32.f16.f16.f32 "
        "{%0,%1,%2,%3}, {%4,%5,%6,%7}, {%8,%9}, {%0,%1,%2,%3};"
        : "+f"(c[0]), "+f"(c[1]), "+f"(c[2]), "+f"(c[3])
        : "r"(a0), "r"(a1), "r"(a2), "r"(a3), "r"(b0), "r"(b1));
}

// k-pair permutation within a 16-halves block:
// src element w (0..15): pair p=w>>1, bit t=w&1; slot s = (p<4) ? 2p : 2(p-4)+1; dst = 2s+t.
// Result: thread t4's LDS.64 at halves offset 4*t4 yields (k-lo pair, k-hi pair) = (frag0, frag1).
__device__ __forceinline__ int kperm(int w) {
    int p = (w >> 1) & 7, t = w & 1;
    int s = (p < 4) ? (p << 1) : (((p - 4) << 1) | 1);
    return (s << 1) | t;
}

// ---------------------------------------------------------------- prep: weights
// g_WT[j][k0 + perm] = fp16( W[k][j] + (k>=2048 ? U[k-2048][j] : 0) )
__global__ void prep_weights_t(const float* __restrict__ Wc, const float* __restrict__ Uc,
                               const float* __restrict__ Wg, const float* __restrict__ Ug) {
    __shared__ float tc[32][33];
    __shared__ float tg[32][33];
    int tx = threadIdx.x, ty = threadIdx.y;        // 32 x 8
    int k0 = blockIdx.x * 32, j0 = blockIdx.y * 32;
    #pragma unroll
    for (int r = 0; r < 4; r++) {
        int kr = k0 + ty + r * 8;
        size_t idx = (size_t)kr * H_DIM + j0 + tx;
        float vc = Wc[idx], vg = Wg[idx];
        if (kr >= H_DIM) {
            size_t iu = (size_t)(kr - H_DIM) * H_DIM + j0 + tx;
            vc += Uc[iu]; vg += Ug[iu];
        }
        tc[ty + r * 8][tx] = vc;
        tg[ty + r * 8][tx] = vg;
    }
    __syncthreads();
    int kp = (tx & 16) | kperm(tx & 15);
    #pragma unroll
    for (int r = 0; r < 4; r++) {
        int jr = j0 + ty + r * 8;
        g_WcT[(size_t)jr * KTOT + k0 + kp] = __float2half_rn(tc[tx][ty + r * 8]);
        g_WgT[(size_t)jr * KTOT + k0 + kp] = __float2half_rn(tg[tx][ty + r * 8]);
    }
}

// ---------------------------------------------------------------- prep: activations
// One thread per 16-k block: fp32 -> fp16 with k-pair permutation.
__global__ void prep_act(const float* __restrict__ x_t, const float* __restrict__ state) {
    size_t i = (size_t)blockIdx.x * blockDim.x + threadIdx.x;   // over B*H/16
    size_t base = i * 16;                                       // element offset
    const float4* xs = (const float4*)(x_t + base);
    const float4* ss = (const float4*)(state + base);
    float fx[16], fs[16];
    #pragma unroll
    for (int q = 0; q < 4; q++) {
        float4 a = xs[q], b = ss[q];
        fx[q*4+0]=a.x; fx[q*4+1]=a.y; fx[q*4+2]=a.z; fx[q*4+3]=a.w;
        fs[q*4+0]=b.x; fs[q*4+1]=b.y; fs[q*4+2]=b.z; fs[q*4+3]=b.w;
    }
    // pairs in permuted order: (0,1),(8,9),(2,3),(10,11),(4,5),(12,13),(6,7),(14,15)
    const int src[8] = {0, 8, 2, 10, 4, 12, 6, 14};
    __half2 hx[8], hs[8];
    #pragma unroll
    for (int p = 0; p < 8; p++) {
        hx[p] = __floats2half2_rn(fx[src[p]], fx[src[p] + 1]);
        hs[p] = __floats2half2_rn(fs[src[p]], fs[src[p] + 1]);
    }
    uint4* ox = (uint4*)(g_xr + base);
    uint4* os = (uint4*)(g_sr + base);
    ox[0] = *(uint4*)&hx[0];  ox[1] = *(uint4*)&hx[4];
    os[0] = *(uint4*)&hs[0];  os[1] = *(uint4*)&hs[4];
}

// ---------------------------------------------------------------- stage loader (256 threads)
__device__ __forceinline__ void load_stage(
    SmemStage& st, int ks, int tid, int rowBase, int colBase)
{
    const int k0 = ks * BK;
    const __half* Asrc; int ka;
    if (k0 < H_DIM) { Asrc = g_xr; ka = k0; }
    else            { Asrc = g_sr; ka = k0 - H_DIM; }
    // A: 128 rows x 32 halves (64B) = 512 x 16B chunks, 2 per thread
    #pragma unroll
    for (int i = 0; i < 2; i++) {
        int c = tid + i * NTHREADS;
        int row = c >> 2, ch = (c & 3) * 8;          // halves offset 0,8,16,24
        cp_async16(&st.A[row * T_LD + ch],
                   Asrc + (size_t)(rowBase + row) * H_DIM + ka + ch);
    }
    // Bc/Bg: 128 n-rows x 32 halves each; 2 chunks of each per thread
    #pragma unroll
    for (int i = 0; i < 2; i++) {
        int c = tid + i * NTHREADS;
        int n = c >> 2, ch = (c & 3) * 8;
        size_t off = (size_t)(colBase + n) * KTOT + k0 + ch;
        cp_async16(&st.Bc[n * T_LD + ch], g_WcT + off);
        cp_async16(&st.Bg[n * T_LD + ch], g_WgT + off);
    }
    cp_commit();
}

// ---------------------------------------------------------------- fused dual-GEMM + gate epilogue
__global__ void __launch_bounds__(NTHREADS, 1)
gemm_kernel(const float* __restrict__ state,
            const float* __restrict__ bc,  const float* __restrict__ bg,
            const float* __restrict__ log_step)
{
    extern __shared__ char smem_raw[];
    SmemStage* smem = (SmemStage*)smem_raw;

    const int rowBase = blockIdx.y * BM;
    const int colBase = blockIdx.x * BN;
    const int tid  = threadIdx.x;
    const int wid  = tid >> 5, lane = tid & 31;
    const int wm   = wid & 1,  wn   = wid >> 1;      // 2 warps along M, 4 along N
    const int g    = lane >> 2, t4  = lane & 3;

    float accC[4][4][4];     // [mt][nt][frag]
    float accG[4][4][4];
    #pragma unroll
    for (int a = 0; a < 4; a++)
        #pragma unroll
        for (int b = 0; b < 4; b++)
            #pragma unroll
            for (int c = 0; c < 4; c++) { accC[a][b][c] = 0.f; accG[a][b][c] = 0.f; }

    for (int s = 0; s < STAGES - 1; s++)
        load_stage(smem[s], s, tid, rowBase, colBase);

    for (int kt = 0; kt < NITER; kt++) {
        cp_wait<STAGES - 2>();
        __syncthreads();                         // stage kt ready; stage kt-1 fully consumed

        int nxt = kt + STAGES - 1;
        if (nxt < NITER)
            load_stage(smem[nxt % STAGES], nxt, tid, rowBase, colBase);
        else
            cp_commit();                         // keep group-count invariant

        SmemStage& st = smem[kt % STAGES];
        #pragma unroll
        for (int kk = 0; kk < 2; kk++) {         // two k16 steps per BK=32 stage
            const int kb = kk * 16 + 4 * t4;     // halves offset of this thread's frag pair
            // A frags: row g -> (a0, a2); row g+8 -> (a1, a3): LDS.64 each
            uint2 aLo[4], aHi[4];
            #pragma unroll
            for (int mt = 0; mt < 4; mt++) {
                int r = wm * 64 + mt * 16 + g;
                aLo[mt] = *(const uint2*)&st.A[r * T_LD + kb];
                aHi[mt] = *(const uint2*)&st.A[(r + 8) * T_LD + kb];
            }
            // B frags: (b0, b1) via LDS.64
            uint2 fc[4], fg[4];
            #pragma unroll
            for (int nt = 0; nt < 4; nt++) {
                int n = wn * 32 + nt * 8 + g;
                fc[nt] = *(const uint2*)&st.Bc[n * T_LD + kb];
                fg[nt] = *(const uint2*)&st.Bg[n * T_LD + kb];
            }
            #pragma unroll
            for (int nt = 0; nt < 4; nt++) {
                #pragma unroll
                for (int mt = 0; mt < 4; mt++) {
                    mma16(accC[mt][nt], aLo[mt].x, aHi[mt].x, aLo[mt].y, aHi[mt].y,
                          fc[nt].x, fc[nt].y);
                    mma16(accG[mt][nt], aLo[mt].x, aHi[mt].x, aLo[mt].y, aHi[mt].y,
                          fg[nt].x, fg[nt].y);
                }
            }
        }
    }

    // Epilogue: h = alpha*state + (1-alpha)*sigmoid(zg)*tanh(zc)  (state read in fp32)
    #pragma unroll
    for (int nt = 0; nt < 4; nt++) {
        int j0 = colBase + wn * 32 + nt * 8 + 2 * t4;
        float bc0 = bc[j0],  bc1 = bc[j0 + 1];
        float bg0 = bg[j0],  bg1 = bg[j0 + 1];
        float al0 = expf(-expf(-log_step[j0]));      // alpha = exp(-1/exp(log_step))
        float al1 = expf(-expf(-log_step[j0 + 1]));
        #pragma unroll
        for (int mt = 0; mt < 4; mt++) {
            int r0 = rowBase + wm * 64 + mt * 16 + g;
            #pragma unroll
            for (int half = 0; half < 2; half++) {
                int r = r0 + half * 8;
                float zc0 = accC[mt][nt][half * 2]     + bc0;
                float zc1 = accC[mt][nt][half * 2 + 1] + bc1;
                float zg0 = accG[mt][nt][half * 2]     + bg0;
                float zg1 = accG[mt][nt][half * 2 + 1] + bg1;
                float s0 = state[(size_t)r * H_DIM + j0];
                float s1 = state[(size_t)r * H_DIM + j0 + 1];
                float cand0 = tanhf(zc0), cand1 = tanhf(zc1);
                float gate0 = 1.f / (1.f + expf(-zg0));
                float gate1 = 1.f / (1.f + expf(-zg1));
                float h0 = al0 * s0 + (1.f - al0) * gate0 * cand0;
                float h1 = al1 * s1 + (1.f - al1) * gate1 * cand1;
                *(float2*)&g_h[(size_t)r * H_DIM + j0] = make_float2(h0, h1);
            }
        }
    }
}

// ---------------------------------------------------------------- layernorm over H=2048
__device__ __forceinline__ float warp_sum(float v) {
    #pragma unroll
    for (int o = 16; o; o >>= 1) v += __shfl_xor_sync(0xffffffffu, v, o);
    return v;
}

__global__ void ln_kernel(const float* __restrict__ gamma, const float* __restrict__ beta,
                          float* __restrict__ out)
{
    int row = blockIdx.x;
    const float4* h = (const float4*)(g_h + (size_t)row * H_DIM);
    float4*       o = (float4*)(out + (size_t)row * H_DIM);
    const float4* gm = (const float4*)gamma;
    const float4* bt = (const float4*)beta;

    int tid = threadIdx.x;
    float4 v0 = h[tid], v1 = h[tid + 256];

    float s  = v0.x + v0.y + v0.z + v0.w + v1.x + v1.y + v1.z + v1.w;
    float sq = v0.x*v0.x + v0.y*v0.y + v0.z*v0.z + v0.w*v0.w
             + v1.x*v1.x + v1.y*v1.y + v1.z*v1.z + v1.w*v1.w;

    s  = warp_sum(s);
    sq = warp_sum(sq);
    __shared__ float sh[16];
    int wid = tid >> 5, lane = tid & 31;
    if (lane == 0) { sh[wid] = s; sh[8 + wid] = sq; }
    __syncthreads();
    float tot = 0.f, totq = 0.f;
    #pragma unroll
    for (int i = 0; i < 8; i++) { tot += sh[i]; totq += sh[8 + i]; }

    float mu  = tot * (1.f / H_DIM);
    float var = totq * (1.f / H_DIM) - mu * mu;
    float inv = rsqrtf(var + 1e-5f);

    float4 g0 = gm[tid], g1 = gm[tid + 256];
    float4 b0 = bt[tid], b1 = bt[tid + 256];
    float4 o0, o1;
    o0.x = (v0.x - mu) * inv * g0.x + b0.x;
    o0.y = (v0.y - mu) * inv * g0.y + b0.y;
    o0.z = (v0.z - mu) * inv * g0.z + b0.z;
    o0.w = (v0.w - mu) * inv * g0.w + b0.w;
    o1.x = (v1.x - mu) * inv * g1.x + b1.x;
    o1.y = (v1.y - mu) * inv * g1.y + b1.y;
    o1.z = (v1.z - mu) * inv * g1.z + b1.z;
    o1.w = (v1.w - mu) * inv * g1.w + b1.w;
    o[tid] = o0;
    o[tid + 256] = o1;
}

// ---------------------------------------------------------------- launch
extern "C" void kernel_launch(void* const* d_in, const int* in_sizes, int n_in,
                              void* d_out, int out_size) {
    const float* x_t      = (const float*)d_in[0];
    const float* state    = (const float*)d_in[1];
    const float* Wc       = (const float*)d_in[2];
    const float* Uc       = (const float*)d_in[3];
    const float* bc       = (const float*)d_in[4];
    const float* Wg       = (const float*)d_in[5];
    const float* Ug       = (const float*)d_in[6];
    const float* bg       = (const float*)d_in[7];
    const float* log_step = (const float*)d_in[8];
    const float* gamma    = (const float*)d_in[9];
    const float* beta     = (const float*)d_in[10];
    float* out = (float*)d_out;

    cudaFuncSetAttribute(gemm_kernel, cudaFuncAttributeMaxDynamicSharedMemorySize, SMEM_TOTAL);

    dim3 pgrid(KTOT / 32, H_DIM / 32);     // (128, 64)
    prep_weights_t<<<pgrid, dim3(32, 8)>>>(Wc, Uc, Wg, Ug);
    prep_act<<<(int)(((size_t)B_DIM * H_DIM / 16) / 256), 256>>>(x_t, state);

    dim3 grid(H_DIM / BN, B_DIM / BM);     // (16, 64) = 1024 CTAs
    gemm_kernel<<<grid, NTHREADS, SMEM_TOTAL>>>(state, bc, bg, log_step);

    ln_kernel<<<B_DIM, 256>>>(gamma, beta, out);
}

// round 9
// speedup vs baseline: 2.3925x; 1.2000x over previous
#include <cuda_runtime.h>
#include <cuda_fp16.h>
#include <cstdint>
#include <math.h>

// ---------------------------------------------------------------- dims
#define B_DIM 8192
#define H_DIM 2048
constexpr int KTOT = 4096;            // folded K: 2048 (x_t) + 2048 (state)

// GEMM tiling (fp16 operands, fp32 accumulate)
constexpr int BM = 128;               // batch rows per CTA
constexpr int BN = 128;               // H cols per CTA (cand & gate both)
constexpr int BK = 32;                // k per stage
constexpr int NSTAGES = 8;
constexpr int NITER = KTOT / BK;      // 128
constexpr int NTHREADS = 256;         // 8 warps: wm = wid&1 (2 along M), wn = wid>>1 (4 along N)

// Tile blob sizes (fragment-ordered, contiguous)
constexpr int A_TILE_BYTES = 8192;    // 128 rows x 32 k x fp16
constexpr int B_TILE_BYTES = 16384;   // (cand 128 + gate 128) cols x 32 k x fp16
constexpr int STAGE_BYTES  = A_TILE_BYTES + B_TILE_BYTES;   // 24576

// smem layout
constexpr int SM_MBAR   = 0;          // 8 x 8B mbarriers
constexpr int SM_STAGE0 = 1024;
constexpr int SMEM_TOTAL = SM_STAGE0 + NSTAGES * STAGE_BYTES;   // 197632

// ---------------------------------------------------------------- scratch (device globals)
// Activations, tiled fragment-order: [rb(64)][ks(128)] -> 8KB blob
__device__ __align__(128) __half g_act[(size_t)64 * 128 * 4096];
// Weights (folded W+U), tiled fragment-order: [cb(16)][ks(128)] -> 16KB blob (Bc 8KB || Bg 8KB)
__device__ __align__(128) __half g_wt [(size_t)16 * 128 * 8192];
__device__ float g_h[(size_t)B_DIM * H_DIM];   // h_new before layernorm

// ---------------------------------------------------------------- PTX helpers
__device__ __forceinline__ uint32_t smem_u32(const void* p) {
    uint32_t a;
    asm("{ .reg .u64 t; cvta.to.shared.u64 t, %1; cvt.u32.u64 %0, t; }" : "=r"(a) : "l"(p));
    return a;
}
__device__ __forceinline__ void mbar_init(uint32_t a, uint32_t cnt) {
    asm volatile("mbarrier.init.shared.b64 [%0], %1;" :: "r"(a), "r"(cnt) : "memory");
}
__device__ __forceinline__ void mbar_expect_tx(uint32_t a, uint32_t bytes) {
    asm volatile("mbarrier.arrive.expect_tx.shared.b64 _, [%0], %1;"
                 :: "r"(a), "r"(bytes) : "memory");
}
__device__ __forceinline__ void mbar_wait(uint32_t a, uint32_t parity) {
    asm volatile(
        "{\n\t.reg .pred P;\n\t"
        "WL_%=:\n\t"
        "mbarrier.try_wait.parity.acquire.cta.shared::cta.b64 P, [%0], %1, 0x989680;\n\t"
        "@!P bra WL_%=;\n\t}"
        :: "r"(a), "r"(parity) : "memory");
}
__device__ __forceinline__ void bulk_g2s(uint32_t dst_s, const void* src, uint32_t bytes,
                                         uint32_t mbar) {
    asm volatile(
        "cp.async.bulk.shared::cluster.global.mbarrier::complete_tx::bytes [%0], [%1], %2, [%3];"
        :: "r"(dst_s), "l"(src), "r"(bytes), "r"(mbar) : "memory");
}
#define FENCE_PROXY_ASYNC() asm volatile("fence.proxy.async.shared::cta;" ::: "memory")
__device__ __forceinline__ void mma16(float* c, uint32_t a0, uint32_t a1, uint32_t a2, uint32_t a3,
                                      uint32_t b0, uint32_t b1) {
    asm volatile(
        "mma.sync.aligned.m16n8k16.row.col.f32.f16.f16.f32 "
        "{%0,%1,%2,%3}, {%4,%5,%6,%7}, {%8,%9}, {%0,%1,%2,%3};"
        : "+f"(c[0]), "+f"(c[1]), "+f"(c[2]), "+f"(c[3])
        : "r"(a0), "r"(a1), "r"(a2), "r"(a3), "r"(b0), "r"(b1));
}
__device__ __forceinline__ uint32_t packh2(__half lo, __half hi) {
    __half2 p = __halves2half2(lo, hi);
    return *(uint32_t*)&p;
}

// ---------------------------------------------------------------- prep: activations
// One CTA per (ks, rb). Emits 8KB fragment-ordered tile:
//   granule gi (16B) = [kk(2)][wm(2)][c(4)][lane(32)]; lane=4g+t4
//   bytes: e0,e1 = row r   k {2t4,2t4+1}; e2,e3 = row r   k {8+2t4,9+2t4}
//          e4..7 = row r+8 same k;   r = wm*64 + c*16 + g  (k rel. to kk*16)
__global__ void prep_act(const float* __restrict__ x_t, const float* __restrict__ state) {
    __shared__ __half sm[128 * 32];
    const int ks = blockIdx.x, rb = blockIdx.y;
    const float* src = (ks < 64) ? x_t : state;
    const int ka = (ks & 63) * 32;
    const int t = threadIdx.x;

    {   // load 128 rows x 32 k fp32 -> fp16 smem
        int row = t >> 1, kq = (t & 1) * 16;
        const float4* s4 = (const float4*)(src + (size_t)(rb * 128 + row) * H_DIM + ka + kq);
        #pragma unroll
        for (int q = 0; q < 4; q++) {
            float4 v = s4[q];
            __half2* d = (__half2*)&sm[row * 32 + kq + q * 4];
            d[0] = __floats2half2_rn(v.x, v.y);
            d[1] = __floats2half2_rn(v.z, v.w);
        }
    }
    __syncthreads();

    uint4* dst = (uint4*)(g_act + ((size_t)rb * 128 + ks) * 4096);
    #pragma unroll
    for (int i = 0; i < 2; i++) {
        int gi = t + i * 256;
        int kk = gi >> 8, rem = gi & 255;
        int wm = rem >> 7, c = (rem >> 5) & 3, lane = rem & 31;
        int g = lane >> 2, t4 = lane & 3;
        int r  = wm * 64 + c * 16 + g;
        int kb = kk * 16 + 2 * t4;
        uint32_t h01 = *(const uint32_t*)&sm[r * 32 + kb];
        uint32_t h23 = *(const uint32_t*)&sm[r * 32 + kb + 8];
        uint32_t h45 = *(const uint32_t*)&sm[(r + 8) * 32 + kb];
        uint32_t h67 = *(const uint32_t*)&sm[(r + 8) * 32 + kb + 8];
        dst[gi] = make_uint4(h01, h23, h45, h67);
    }
}

// ---------------------------------------------------------------- prep: weights
// One CTA per (ks, cb). Emits 16KB tile: Bc (8KB) then Bg (8KB), each:
//   granule gi = [kk(2)][wn(4)][cc(2)][lane(32)]; lane=4g+t4
//   e0,e1 = col j_lo k {2t4,2t4+1}; e2,e3 = col j_lo k {8+2t4,..}; e4..7 = col j_hi
//   j_lo = wn*32 + 2cc*8 + g; j_hi = j_lo + 8
__global__ void prep_w(const float* __restrict__ Wc, const float* __restrict__ Uc,
                       const float* __restrict__ Wg, const float* __restrict__ Ug) {
    __shared__ __half smc[32 * 128];
    __shared__ __half smg[32 * 128];
    const int ks = blockIdx.x, cb = blockIdx.y;
    const int k0 = ks * 32, j0 = cb * 128;
    const int t = threadIdx.x;

    {   // load 32 k-rows x 128 j, fold U, -> fp16 smem [k][j]
        int kr = t >> 3, jq = (t & 7) * 16;
        int kg = k0 + kr;
        const float4* wc4 = (const float4*)(Wc + (size_t)kg * H_DIM + j0 + jq);
        const float4* wg4 = (const float4*)(Wg + (size_t)kg * H_DIM + j0 + jq);
        bool fold = (kg >= H_DIM);
        const float4* uc4 = (const float4*)(Uc + (size_t)(kg - H_DIM) * H_DIM + j0 + jq);
        const float4* ug4 = (const float4*)(Ug + (size_t)(kg - H_DIM) * H_DIM + j0 + jq);
        #pragma unroll
        for (int q = 0; q < 4; q++) {
            float4 a = wc4[q], b = wg4[q];
            if (fold) {
                float4 u = uc4[q], v = ug4[q];
                a.x += u.x; a.y += u.y; a.z += u.z; a.w += u.w;
                b.x += v.x; b.y += v.y; b.z += v.z; b.w += v.w;
            }
            __half2* dc = (__half2*)&smc[kr * 128 + jq + q * 4];
            __half2* dg = (__half2*)&smg[kr * 128 + jq + q * 4];
            dc[0] = __floats2half2_rn(a.x, a.y); dc[1] = __floats2half2_rn(a.z, a.w);
            dg[0] = __floats2half2_rn(b.x, b.y); dg[1] = __floats2half2_rn(b.z, b.w);
        }
    }
    __syncthreads();

    uint4* dst = (uint4*)(g_wt + ((size_t)cb * 128 + ks) * 8192);
    #pragma unroll
    for (int i = 0; i < 4; i++) {
        int gi = t + i * 256;                       // 0..1023
        int m  = gi >> 9, rem = gi & 511;
        int kk = rem >> 8, wn = (rem >> 6) & 3, cc = (rem >> 5) & 1, lane = rem & 31;
        int g = lane >> 2, t4 = lane & 3;
        const __half* sm = m ? smg : smc;
        int jlo = wn * 32 + (2 * cc) * 8 + g;
        int jhi = jlo + 8;
        int kb  = kk * 16 + 2 * t4;
        uint32_t e01 = packh2(sm[kb * 128 + jlo],       sm[(kb + 1) * 128 + jlo]);
        uint32_t e23 = packh2(sm[(kb + 8) * 128 + jlo], sm[(kb + 9) * 128 + jlo]);
        uint32_t e45 = packh2(sm[kb * 128 + jhi],       sm[(kb + 1) * 128 + jhi]);
        uint32_t e67 = packh2(sm[(kb + 8) * 128 + jhi], sm[(kb + 9) * 128 + jhi]);
        dst[gi] = make_uint4(e01, e23, e45, e67);
    }
}

// ---------------------------------------------------------------- main GEMM
__global__ void __launch_bounds__(NTHREADS, 1)
gemm_kernel(const float* __restrict__ state,
            const float* __restrict__ bc,  const float* __restrict__ bg,
            const float* __restrict__ log_step)
{
    extern __shared__ char smem[];
    const uint32_t sb = smem_u32(smem);
    const int tid = threadIdx.x, wid = tid >> 5, lane = tid & 31;
    const int wm = wid & 1, wn = wid >> 1;
    const int g  = lane >> 2, t4 = lane & 3;
    const int rowBase = blockIdx.y * BM;
    const int colBase = blockIdx.x * BN;

    const __half* actT = g_act + (size_t)blockIdx.y * (128 * 4096);
    const __half* wT   = g_wt  + (size_t)blockIdx.x * (128 * 8192);

    if (tid == 0) {
        for (int s = 0; s < NSTAGES; s++) mbar_init(sb + SM_MBAR + s * 8, 1);
    }
    __syncthreads();

    auto issue = [&](int ks) {
        uint32_t mb  = sb + SM_MBAR + (ks % NSTAGES) * 8;
        uint32_t dst = sb + SM_STAGE0 + (ks % NSTAGES) * STAGE_BYTES;
        mbar_expect_tx(mb, STAGE_BYTES);
        bulk_g2s(dst,                actT + (size_t)ks * 4096, A_TILE_BYTES, mb);
        bulk_g2s(dst + A_TILE_BYTES, wT   + (size_t)ks * 8192, B_TILE_BYTES, mb);
    };

    if (tid == 0) {
        FENCE_PROXY_ASYNC();
        for (int s = 0; s < NSTAGES - 1; s++) issue(s);
    }

    float accC[4][4][4];
    float accG[4][4][4];
    #pragma unroll
    for (int a = 0; a < 4; a++)
        #pragma unroll
        for (int b = 0; b < 4; b++)
            #pragma unroll
            for (int c = 0; c < 4; c++) { accC[a][b][c] = 0.f; accG[a][b][c] = 0.f; }

    for (int kt = 0; kt < NITER; kt++) {
        __syncthreads();                        // everyone done with stage kt-1's slot
        int nxt = kt + NSTAGES - 1;
        if (tid == 0 && nxt < NITER) {
            FENCE_PROXY_ASYNC();
            issue(nxt);
        }
        mbar_wait(sb + SM_MBAR + (kt % NSTAGES) * 8, (uint32_t)((kt / NSTAGES) & 1));

        const char* st = smem + SM_STAGE0 + (kt % NSTAGES) * STAGE_BYTES;
        #pragma unroll
        for (int kk = 0; kk < 2; kk++) {
            const uint4* pA = (const uint4*)(st + kk * 4096 + wm * 2048 + lane * 16);
            uint4 VA[4];
            #pragma unroll
            for (int c = 0; c < 4; c++) VA[c] = pA[c * 32];      // c stride 512B

            const uint4* pC = (const uint4*)(st + A_TILE_BYTES + kk * 4096
                                             + wn * 1024 + lane * 16);
            const uint4* pG = (const uint4*)(st + A_TILE_BYTES + 8192 + kk * 4096
                                             + wn * 1024 + lane * 16);
            uint4 VC[2], VG[2];
            VC[0] = pC[0]; VC[1] = pC[32];
            VG[0] = pG[0]; VG[1] = pG[32];

            #pragma unroll
            for (int cc = 0; cc < 2; cc++) {
                #pragma unroll
                for (int mt = 0; mt < 4; mt++) {
                    // a0 = row g k-lo, a1 = row g+8 k-lo, a2 = row g k-hi, a3 = row g+8 k-hi
                    mma16(accC[mt][2 * cc],     VA[mt].x, VA[mt].z, VA[mt].y, VA[mt].w,
                          VC[cc].x, VC[cc].y);
                    mma16(accC[mt][2 * cc + 1], VA[mt].x, VA[mt].z, VA[mt].y, VA[mt].w,
                          VC[cc].z, VC[cc].w);
                    mma16(accG[mt][2 * cc],     VA[mt].x, VA[mt].z, VA[mt].y, VA[mt].w,
                          VG[cc].x, VG[cc].y);
                    mma16(accG[mt][2 * cc + 1], VA[mt].x, VA[mt].z, VA[mt].y, VA[mt].w,
                          VG[cc].z, VG[cc].w);
                }
            }
        }
    }

    // Epilogue: h = alpha*state + (1-alpha)*sigmoid(zg)*tanh(zc)
    #pragma unroll
    for (int nt = 0; nt < 4; nt++) {
        int j0 = colBase + wn * 32 + nt * 8 + 2 * t4;
        float bc0 = bc[j0],  bc1 = bc[j0 + 1];
        float bg0 = bg[j0],  bg1 = bg[j0 + 1];
        float al0 = expf(-expf(-log_step[j0]));      // alpha = exp(-1/exp(log_step))
        float al1 = expf(-expf(-log_step[j0 + 1]));
        #pragma unroll
        for (int mt = 0; mt < 4; mt++) {
            int r0 = rowBase + wm * 64 + mt * 16 + g;
            #pragma unroll
            for (int half = 0; half < 2; half++) {
                int r = r0 + half * 8;
                float zc0 = accC[mt][nt][half * 2]     + bc0;
                float zc1 = accC[mt][nt][half * 2 + 1] + bc1;
                float zg0 = accG[mt][nt][half * 2]     + bg0;
                float zg1 = accG[mt][nt][half * 2 + 1] + bg1;
                float s0 = state[(size_t)r * H_DIM + j0];
                float s1 = state[(size_t)r * H_DIM + j0 + 1];
                float cand0 = tanhf(zc0), cand1 = tanhf(zc1);
                float gate0 = 1.f / (1.f + expf(-zg0));
                float gate1 = 1.f / (1.f + expf(-zg1));
                float h0 = al0 * s0 + (1.f - al0) * gate0 * cand0;
                float h1 = al1 * s1 + (1.f - al1) * gate1 * cand1;
                *(float2*)&g_h[(size_t)r * H_DIM + j0] = make_float2(h0, h1);
            }
        }
    }
}

// ---------------------------------------------------------------- layernorm over H=2048
__device__ __forceinline__ float warp_sum(float v) {
    #pragma unroll
    for (int o = 16; o; o >>= 1) v += __shfl_xor_sync(0xffffffffu, v, o);
    return v;
}

__global__ void ln_kernel(const float* __restrict__ gamma, const float* __restrict__ beta,
                          float* __restrict__ out)
{
    int row = blockIdx.x;
    const float4* h = (const float4*)(g_h + (size_t)row * H_DIM);
    float4*       o = (float4*)(out + (size_t)row * H_DIM);
    const float4* gm = (const float4*)gamma;
    const float4* bt = (const float4*)beta;

    int tid = threadIdx.x;
    float4 v0 = h[tid], v1 = h[tid + 256];

    float s  = v0.x + v0.y + v0.z + v0.w + v1.x + v1.y + v1.z + v1.w;
    float sq = v0.x*v0.x + v0.y*v0.y + v0.z*v0.z + v0.w*v0.w
             + v1.x*v1.x + v1.y*v1.y + v1.z*v1.z + v1.w*v1.w;

    s  = warp_sum(s);
    sq = warp_sum(sq);
    __shared__ float sh[16];
    int wid = tid >> 5, lane = tid & 31;
    if (lane == 0) { sh[wid] = s; sh[8 + wid] = sq; }
    __syncthreads();
    float tot = 0.f, totq = 0.f;
    #pragma unroll
    for (int i = 0; i < 8; i++) { tot += sh[i]; totq += sh[8 + i]; }

    float mu  = tot * (1.f / H_DIM);
    float var = totq * (1.f / H_DIM) - mu * mu;
    float inv = rsqrtf(var + 1e-5f);

    float4 g0 = gm[tid], g1 = gm[tid + 256];
    float4 b0 = bt[tid], b1 = bt[tid + 256];
    float4 o0, o1;
    o0.x = (v0.x - mu) * inv * g0.x + b0.x;
    o0.y = (v0.y - mu) * inv * g0.y + b0.y;
    o0.z = (v0.z - mu) * inv * g0.z + b0.z;
    o0.w = (v0.w - mu) * inv * g0.w + b0.w;
    o1.x = (v1.x - mu) * inv * g1.x + b1.x;
    o1.y = (v1.y - mu) * inv * g1.y + b1.y;
    o1.z = (v1.z - mu) * inv * g1.z + b1.z;
    o1.w = (v1.w - mu) * inv * g1.w + b1.w;
    o[tid] = o0;
    o[tid + 256] = o1;
}

// ---------------------------------------------------------------- launch
extern "C" void kernel_launch(void* const* d_in, const int* in_sizes, int n_in,
                              void* d_out, int out_size) {
    const float* x_t      = (const float*)d_in[0];
    const float* state    = (const float*)d_in[1];
    const float* Wc       = (const float*)d_in[2];
    const float* Uc       = (const float*)d_in[3];
    const float* bc       = (const float*)d_in[4];
    const float* Wg       = (const float*)d_in[5];
    const float* Ug       = (const float*)d_in[6];
    const float* bg       = (const float*)d_in[7];
    const float* log_step = (const float*)d_in[8];
    const float* gamma    = (const float*)d_in[9];
    const float* beta     = (const float*)d_in[10];
    float* out = (float*)d_out;

    cudaFuncSetAttribute(gemm_kernel, cudaFuncAttributeMaxDynamicSharedMemorySize, SMEM_TOTAL);

    prep_act<<<dim3(128, 64), 256>>>(x_t, state);
    prep_w  <<<dim3(128, 16), 256>>>(Wc, Uc, Wg, Ug);

    dim3 grid(H_DIM / BN, B_DIM / BM);     // (16, 64) = 1024 CTAs
    gemm_kernel<<<grid, NTHREADS, SMEM_TOTAL>>>(state, bc, bg, log_step);

    ln_kernel<<<B_DIM, 256>>>(gamma, beta, out);
}

// round 11
// speedup vs baseline: 2.4866x; 1.0393x over previous
#include <cuda_runtime.h>
#include <cuda_fp16.h>
#include <cstdint>
#include <math.h>

// ---------------------------------------------------------------- dims
#define B_DIM 8192
#define H_DIM 2048
constexpr int KTOT = 4096;            // folded K: 2048 (x_t) + 2048 (state)

// GEMM tiling (fp16 operands, fp32 accumulate)
constexpr int BM = 128;               // batch rows per CTA
constexpr int BN = 128;               // H cols per CTA (cand & gate both)
constexpr int BK = 32;                // k per stage
constexpr int NSTAGES = 8;
constexpr int NITER = KTOT / BK;      // 128
constexpr int NTHREADS = 256;         // 8 warps: wm = wid&1 (2 along M), wn = wid>>1 (4 along N)

// Tile blob sizes (fragment-ordered, contiguous)
constexpr int A_TILE_BYTES = 8192;    // 128 rows x 32 k x fp16
constexpr int B_TILE_BYTES = 16384;   // (cand 128 + gate 128) cols x 32 k x fp16
constexpr int STAGE_BYTES  = A_TILE_BYTES + B_TILE_BYTES;   // 24576

// smem layout
constexpr int SM_MBAR   = 0;          // 8 x 8B mbarriers
constexpr int SM_STAGE0 = 1024;
constexpr int SMEM_TOTAL = SM_STAGE0 + NSTAGES * STAGE_BYTES;   // 197632

// ---------------------------------------------------------------- scratch (device globals)
// Activations, tiled fragment-order: [rb(64)][ks(128)] -> 8KB blob
__device__ __align__(128) __half g_act[(size_t)64 * 128 * 4096];
// Weights (folded W+U), tiled fragment-order: [cb(16)][ks(128)] -> 16KB blob (Bc 8KB || Bg 8KB)
__device__ __align__(128) __half g_wt [(size_t)16 * 128 * 8192];
__device__ float g_h[(size_t)B_DIM * H_DIM];   // h_new before layernorm

// ---------------------------------------------------------------- PTX helpers
__device__ __forceinline__ uint32_t smem_u32(const void* p) {
    uint32_t a;
    asm("{ .reg .u64 t; cvta.to.shared.u64 t, %1; cvt.u32.u64 %0, t; }" : "=r"(a) : "l"(p));
    return a;
}
__device__ __forceinline__ void mbar_init(uint32_t a, uint32_t cnt) {
    asm volatile("mbarrier.init.shared.b64 [%0], %1;" :: "r"(a), "r"(cnt) : "memory");
}
__device__ __forceinline__ void mbar_expect_tx(uint32_t a, uint32_t bytes) {
    asm volatile("mbarrier.arrive.expect_tx.shared.b64 _, [%0], %1;"
                 :: "r"(a), "r"(bytes) : "memory");
}
__device__ __forceinline__ void mbar_wait(uint32_t a, uint32_t parity) {
    asm volatile(
        "{\n\t.reg .pred P;\n\t"
        "WL_%=:\n\t"
        "mbarrier.try_wait.parity.acquire.cta.shared::cta.b64 P, [%0], %1, 0x989680;\n\t"
        "@!P bra WL_%=;\n\t}"
        :: "r"(a), "r"(parity) : "memory");
}
__device__ __forceinline__ void bulk_g2s(uint32_t dst_s, const void* src, uint32_t bytes,
                                         uint32_t mbar) {
    asm volatile(
        "cp.async.bulk.shared::cluster.global.mbarrier::complete_tx::bytes [%0], [%1], %2, [%3];"
        :: "r"(dst_s), "l"(src), "r"(bytes), "r"(mbar) : "memory");
}
#define FENCE_PROXY_ASYNC() asm volatile("fence.proxy.async.shared::cta;" ::: "memory")
__device__ __forceinline__ void mma16(float* c, uint32_t a0, uint32_t a1, uint32_t a2, uint32_t a3,
                                      uint32_t b0, uint32_t b1) {
    asm volatile(
        "mma.sync.aligned.m16n8k16.row.col.f32.f16.f16.f32 "
        "{%0,%1,%2,%3}, {%4,%5,%6,%7}, {%8,%9}, {%0,%1,%2,%3};"
        : "+f"(c[0]), "+f"(c[1]), "+f"(c[2]), "+f"(c[3])
        : "r"(a0), "r"(a1), "r"(a2), "r"(a3), "r"(b0), "r"(b1));
}
__device__ __forceinline__ uint32_t packh2(__half lo, __half hi) {
    __half2 p = __halves2half2(lo, hi);
    return *(uint32_t*)&p;
}

// ---------------------------------------------------------------- fused prep
// bid < 8192: activation tile (ks = bid&127, rb = bid>>7) -> 8KB fragment-ordered blob
//   granule gi (16B) = [kk(2)][wm(2)][c(4)][lane(32)]; lane=4g+t4
//   e0,e1 = row r k {2t4,2t4+1}; e2,e3 = row r k {8+2t4,9+2t4}; e4..7 = row r+8 same k
//   r = wm*64 + c*16 + g (k rel. to kk*16)
// bid >= 8192: weight tile (ks = b&127, cb = b>>7) -> 16KB blob: Bc (8KB) then Bg (8KB)
//   granule gi = [kk(2)][wn(4)][cc(2)][lane(32)]; j_lo = wn*32 + 2cc*8 + g; j_hi = j_lo+8
__global__ void prep_all(const float* __restrict__ x_t, const float* __restrict__ state,
                         const float* __restrict__ Wc, const float* __restrict__ Uc,
                         const float* __restrict__ Wg, const float* __restrict__ Ug) {
    __shared__ __half sm[8192];       // act uses first 4096; weights use 4096 + 4096
    const int bid = blockIdx.x;
    const int t = threadIdx.x;

    if (bid < 8192) {
        // ------------- activation tile -------------
        const int ks = bid & 127, rb = bid >> 7;
        const float* src = (ks < 64) ? x_t : state;
        const int ka = (ks & 63) * 32;

        {   // load 128 rows x 32 k fp32 -> fp16 smem
            int row = t >> 1, kq = (t & 1) * 16;
            const float4* s4 = (const float4*)(src + (size_t)(rb * 128 + row) * H_DIM + ka + kq);
            #pragma unroll
            for (int q = 0; q < 4; q++) {
                float4 v = s4[q];
                __half2* d = (__half2*)&sm[row * 32 + kq + q * 4];
                d[0] = __floats2half2_rn(v.x, v.y);
                d[1] = __floats2half2_rn(v.z, v.w);
            }
        }
        __syncthreads();

        uint4* dst = (uint4*)(g_act + ((size_t)rb * 128 + ks) * 4096);
        #pragma unroll
        for (int i = 0; i < 2; i++) {
            int gi = t + i * 256;
            int kk = gi >> 8, rem = gi & 255;
            int wm = rem >> 7, c = (rem >> 5) & 3, lane = rem & 31;
            int g = lane >> 2, t4 = lane & 3;
            int r  = wm * 64 + c * 16 + g;
            int kb = kk * 16 + 2 * t4;
            uint32_t h01 = *(const uint32_t*)&sm[r * 32 + kb];
            uint32_t h23 = *(const uint32_t*)&sm[r * 32 + kb + 8];
            uint32_t h45 = *(const uint32_t*)&sm[(r + 8) * 32 + kb];
            uint32_t h67 = *(const uint32_t*)&sm[(r + 8) * 32 + kb + 8];
            dst[gi] = make_uint4(h01, h23, h45, h67);
        }
    } else {
        // ------------- weight tile -------------
        const int b = bid - 8192;
        const int ks = b & 127, cb = b >> 7;
        const int k0 = ks * 32, j0 = cb * 128;
        __half* smc = sm;            // [k(32)][j(128)]
        __half* smg = sm + 4096;

        {   // load 32 k-rows x 128 j, fold U, -> fp16 smem
            int kr = t >> 3, jq = (t & 7) * 16;
            int kg = k0 + kr;
            const float4* wc4 = (const float4*)(Wc + (size_t)kg * H_DIM + j0 + jq);
            const float4* wg4 = (const float4*)(Wg + (size_t)kg * H_DIM + j0 + jq);
            bool fold = (kg >= H_DIM);
            const float4* uc4 = (const float4*)(Uc + (size_t)(kg - H_DIM) * H_DIM + j0 + jq);
            const float4* ug4 = (const float4*)(Ug + (size_t)(kg - H_DIM) * H_DIM + j0 + jq);
            #pragma unroll
            for (int q = 0; q < 4; q++) {
                float4 a = wc4[q], bb = wg4[q];
                if (fold) {
                    float4 u = uc4[q], v = ug4[q];
                    a.x += u.x; a.y += u.y; a.z += u.z; a.w += u.w;
                    bb.x += v.x; bb.y += v.y; bb.z += v.z; bb.w += v.w;
                }
                __half2* dc = (__half2*)&smc[kr * 128 + jq + q * 4];
                __half2* dg = (__half2*)&smg[kr * 128 + jq + q * 4];
                dc[0] = __floats2half2_rn(a.x, a.y);  dc[1] = __floats2half2_rn(a.z, a.w);
                dg[0] = __floats2half2_rn(bb.x, bb.y); dg[1] = __floats2half2_rn(bb.z, bb.w);
            }
        }
        __syncthreads();

        uint4* dst = (uint4*)(g_wt + ((size_t)cb * 128 + ks) * 8192);
        #pragma unroll
        for (int i = 0; i < 4; i++) {
            int gi = t + i * 256;                       // 0..1023
            int m  = gi >> 9, rem = gi & 511;
            int kk = rem >> 8, wn = (rem >> 6) & 3, cc = (rem >> 5) & 1, lane = rem & 31;
            int g = lane >> 2, t4 = lane & 3;
            const __half* s = m ? smg : smc;
            int jlo = wn * 32 + (2 * cc) * 8 + g;
            int jhi = jlo + 8;
            int kb  = kk * 16 + 2 * t4;
            uint32_t e01 = packh2(s[kb * 128 + jlo],       s[(kb + 1) * 128 + jlo]);
            uint32_t e23 = packh2(s[(kb + 8) * 128 + jlo], s[(kb + 9) * 128 + jlo]);
            uint32_t e45 = packh2(s[kb * 128 + jhi],       s[(kb + 1) * 128 + jhi]);
            uint32_t e67 = packh2(s[(kb + 8) * 128 + jhi], s[(kb + 9) * 128 + jhi]);
            dst[gi] = make_uint4(e01, e23, e45, e67);
        }
    }
}

// ---------------------------------------------------------------- main GEMM
__global__ void __launch_bounds__(NTHREADS, 1)
gemm_kernel(const float* __restrict__ state,
            const float* __restrict__ bc,  const float* __restrict__ bg,
            const float* __restrict__ log_step)
{
    extern __shared__ char smem[];
    const uint32_t sb = smem_u32(smem);
    const int tid = threadIdx.x, wid = tid >> 5, lane = tid & 31;
    const int wm = wid & 1, wn = wid >> 1;
    const int g  = lane >> 2, t4 = lane & 3;
    const int rowBase = blockIdx.y * BM;
    const int colBase = blockIdx.x * BN;

    const __half* actT = g_act + (size_t)blockIdx.y * (128 * 4096);
    const __half* wT   = g_wt  + (size_t)blockIdx.x * (128 * 8192);

    if (tid == 0) {
        for (int s = 0; s < NSTAGES; s++) mbar_init(sb + SM_MBAR + s * 8, 1);
    }
    __syncthreads();

    auto issue = [&](int ks) {
        uint32_t mb  = sb + SM_MBAR + (ks % NSTAGES) * 8;
        uint32_t dst = sb + SM_STAGE0 + (ks % NSTAGES) * STAGE_BYTES;
        mbar_expect_tx(mb, STAGE_BYTES);
        bulk_g2s(dst,                actT + (size_t)ks * 4096, A_TILE_BYTES, mb);
        bulk_g2s(dst + A_TILE_BYTES, wT   + (size_t)ks * 8192, B_TILE_BYTES, mb);
    };

    if (tid == 0) {
        FENCE_PROXY_ASYNC();
        for (int s = 0; s < 6; s++) issue(s);    // 6-deep prologue; pairs keep depth 6-7
    }

    float accC[4][4][4];
    float accG[4][4][4];
    #pragma unroll
    for (int a = 0; a < 4; a++)
        #pragma unroll
        for (int b = 0; b < 4; b++)
            #pragma unroll
            for (int c = 0; c < 4; c++) { accC[a][b][c] = 0.f; accG[a][b][c] = 0.f; }

    auto consume = [&](int kt) {
        const char* st = smem + SM_STAGE0 + (kt % NSTAGES) * STAGE_BYTES;
        #pragma unroll
        for (int kk = 0; kk < 2; kk++) {
            const uint4* pA = (const uint4*)(st + kk * 4096 + wm * 2048 + lane * 16);
            uint4 VA[4];
            #pragma unroll
            for (int c = 0; c < 4; c++) VA[c] = pA[c * 32];      // c stride 512B

            const uint4* pC = (const uint4*)(st + A_TILE_BYTES + kk * 4096
                                             + wn * 1024 + lane * 16);
            const uint4* pG = (const uint4*)(st + A_TILE_BYTES + 8192 + kk * 4096
                                             + wn * 1024 + lane * 16);
            uint4 VC[2], VG[2];
            VC[0] = pC[0]; VC[1] = pC[32];
            VG[0] = pG[0]; VG[1] = pG[32];

            #pragma unroll
            for (int cc = 0; cc < 2; cc++) {
                #pragma unroll
                for (int mt = 0; mt < 4; mt++) {
                    // a0 = row g k-lo, a1 = row g+8 k-lo, a2 = row g k-hi, a3 = row g+8 k-hi
                    mma16(accC[mt][2 * cc],     VA[mt].x, VA[mt].z, VA[mt].y, VA[mt].w,
                          VC[cc].x, VC[cc].y);
                    mma16(accC[mt][2 * cc + 1], VA[mt].x, VA[mt].z, VA[mt].y, VA[mt].w,
                          VC[cc].z, VC[cc].w);
                    mma16(accG[mt][2 * cc],     VA[mt].x, VA[mt].z, VA[mt].y, VA[mt].w,
                          VG[cc].x, VG[cc].y);
                    mma16(accG[mt][2 * cc + 1], VA[mt].x, VA[mt].z, VA[mt].y, VA[mt].w,
                          VG[cc].z, VG[cc].w);
                }
            }
        }
    };

    for (int kt = 0; kt < NITER; kt += 2) {
        __syncthreads();                        // all warps done with pair kt-2,kt-1
        if (tid == 0) {
            FENCE_PROXY_ASYNC();
            if (kt + 6 < NITER) issue(kt + 6);  // slot (kt-2)%8: consumed before sync
            if (kt + 7 < NITER) issue(kt + 7);  // slot (kt-1)%8: consumed before sync
        }
        mbar_wait(sb + SM_MBAR + (kt % NSTAGES) * 8, (uint32_t)((kt >> 3) & 1));
        consume(kt);
        mbar_wait(sb + SM_MBAR + ((kt + 1) % NSTAGES) * 8, (uint32_t)(((kt + 1) >> 3) & 1));
        consume(kt + 1);
    }

    // Epilogue: h = alpha*state + (1-alpha)*sigmoid(zg)*tanh(zc)
    #pragma unroll
    for (int nt = 0; nt < 4; nt++) {
        int j0 = colBase + wn * 32 + nt * 8 + 2 * t4;
        float bc0 = bc[j0],  bc1 = bc[j0 + 1];
        float bg0 = bg[j0],  bg1 = bg[j0 + 1];
        float al0 = expf(-expf(-log_step[j0]));      // alpha = exp(-1/exp(log_step))
        float al1 = expf(-expf(-log_step[j0 + 1]));
        #pragma unroll
        for (int mt = 0; mt < 4; mt++) {
            int r0 = rowBase + wm * 64 + mt * 16 + g;
            #pragma unroll
            for (int half = 0; half < 2; half++) {
                int r = r0 + half * 8;
                float zc0 = accC[mt][nt][half * 2]     + bc0;
                float zc1 = accC[mt][nt][half * 2 + 1] + bc1;
                float zg0 = accG[mt][nt][half * 2]     + bg0;
                float zg1 = accG[mt][nt][half * 2 + 1] + bg1;
                float s0 = state[(size_t)r * H_DIM + j0];
                float s1 = state[(size_t)r * H_DIM + j0 + 1];
                float cand0 = tanhf(zc0), cand1 = tanhf(zc1);
                float gate0 = 1.f / (1.f + expf(-zg0));
                float gate1 = 1.f / (1.f + expf(-zg1));
                float h0 = al0 * s0 + (1.f - al0) * gate0 * cand0;
                float h1 = al1 * s1 + (1.f - al1) * gate1 * cand1;
                *(float2*)&g_h[(size_t)r * H_DIM + j0] = make_float2(h0, h1);
            }
        }
    }
}

// ---------------------------------------------------------------- layernorm over H=2048
__device__ __forceinline__ float warp_sum(float v) {
    #pragma unroll
    for (int o = 16; o; o >>= 1) v += __shfl_xor_sync(0xffffffffu, v, o);
    return v;
}

__global__ void ln_kernel(const float* __restrict__ gamma, const float* __restrict__ beta,
                          float* __restrict__ out)
{
    int row = blockIdx.x;
    const float4* h = (const float4*)(g_h + (size_t)row * H_DIM);
    float4*       o = (float4*)(out + (size_t)row * H_DIM);
    const float4* gm = (const float4*)gamma;
    const float4* bt = (const float4*)beta;

    int tid = threadIdx.x;
    float4 v0 = h[tid], v1 = h[tid + 256];

    float s  = v0.x + v0.y + v0.z + v0.w + v1.x + v1.y + v1.z + v1.w;
    float sq = v0.x*v0.x + v0.y*v0.y + v0.z*v0.z + v0.w*v0.w
             + v1.x*v1.x + v1.y*v1.y + v1.z*v1.z + v1.w*v1.w;

    s  = warp_sum(s);
    sq = warp_sum(sq);
    __shared__ float sh[16];
    int wid = tid >> 5, lane = tid & 31;
    if (lane == 0) { sh[wid] = s; sh[8 + wid] = sq; }
    __syncthreads();
    float tot = 0.f, totq = 0.f;
    #pragma unroll
    for (int i = 0; i < 8; i++) { tot += sh[i]; totq += sh[8 + i]; }

    float mu  = tot * (1.f / H_DIM);
    float var = totq * (1.f / H_DIM) - mu * mu;
    float inv = rsqrtf(var + 1e-5f);

    float4 g0 = gm[tid], g1 = gm[tid + 256];
    float4 b0 = bt[tid], b1 = bt[tid + 256];
    float4 o0, o1;
    o0.x = (v0.x - mu) * inv * g0.x + b0.x;
    o0.y = (v0.y - mu) * inv * g0.y + b0.y;
    o0.z = (v0.z - mu) * inv * g0.z + b0.z;
    o0.w = (v0.w - mu) * inv * g0.w + b0.w;
    o1.x = (v1.x - mu) * inv * g1.x + b1.x;
    o1.y = (v1.y - mu) * inv * g1.y + b1.y;
    o1.z = (v1.z - mu) * inv * g1.z + b1.z;
    o1.w = (v1.w - mu) * inv * g1.w + b1.w;
    o[tid] = o0;
    o[tid + 256] = o1;
}

// ---------------------------------------------------------------- launch
extern "C" void kernel_launch(void* const* d_in, const int* in_sizes, int n_in,
                              void* d_out, int out_size) {
    const float* x_t      = (const float*)d_in[0];
    const float* state    = (const float*)d_in[1];
    const float* Wc       = (const float*)d_in[2];
    const float* Uc       = (const float*)d_in[3];
    const float* bc       = (const float*)d_in[4];
    const float* Wg       = (const float*)d_in[5];
    const float* Ug       = (const float*)d_in[6];
    const float* bg       = (const float*)d_in[7];
    const float* log_step = (const float*)d_in[8];
    const float* gamma    = (const float*)d_in[9];
    const float* beta     = (const float*)d_in[10];
    float* out = (float*)d_out;

    cudaFuncSetAttribute(gemm_kernel, cudaFuncAttributeMaxDynamicSharedMemorySize, SMEM_TOTAL);

    prep_all<<<8192 + 2048, 256>>>(x_t, state, Wc, Uc, Wg, Ug);

    dim3 grid(H_DIM / BN, B_DIM / BM);     // (16, 64) = 1024 CTAs
    gemm_kernel<<<grid, NTHREADS, SMEM_TOTAL>>>(state, bc, bg, log_step);

    ln_kernel<<<B_DIM, 256>>>(gamma, beta, out);
}